// round 7
// baseline (speedup 1.0000x reference)
#include <cuda_runtime.h>
#include <cuda_fp16.h>
#include <stdint.h>

#define IN_F  4096
#define OUT_F 4096
#define BATCH 4096

// ---------------- scratch (static device globals; no allocation) ----------------
__device__ __align__(16) __half g_wh[(size_t)OUT_F * IN_F];   // 32 MB
__device__ __align__(16) __half g_xh[(size_t)BATCH * IN_F];   // 32 MB
__device__ float g_rowsum[BATCH];
__device__ int   g_wmm[2];    // weight q min, max
__device__ int   g_bmm[2];    // bias   q min, max
__device__ float g_scal[4];   // s_w, off_w, s_b, off_b

// ---------------- PTX helpers (legal at compute_103) ----------------
__device__ __forceinline__ uint32_t smem_u32(const void* p) {
    uint32_t a;
    asm("{ .reg .u64 t; cvta.to.shared.u64 t, %1; cvt.u32.u64 %0, t; }" : "=r"(a) : "l"(p));
    return a;
}

#define CP_ASYNC16(dst, src) \
    asm volatile("cp.async.cg.shared.global [%0], [%1], 16;" :: "r"(dst), "l"(src))
#define CP_COMMIT() asm volatile("cp.async.commit_group;" ::: "memory")
#define CP_WAIT(n)  asm volatile("cp.async.wait_group %0;" :: "n"(n) : "memory")

__device__ __forceinline__ void ldsm_x4(uint32_t& d0, uint32_t& d1, uint32_t& d2, uint32_t& d3,
                                        uint32_t addr) {
    asm volatile("ldmatrix.sync.aligned.m8n8.x4.shared.b16 {%0,%1,%2,%3}, [%4];"
                 : "=r"(d0), "=r"(d1), "=r"(d2), "=r"(d3) : "r"(addr));
}

// fp16-accumulate MMA: D(f16x2 x2) += A*B
__device__ __forceinline__ void mma16816h(uint32_t& c0, uint32_t& c1,
                                          uint32_t a0, uint32_t a1, uint32_t a2, uint32_t a3,
                                          uint32_t b0, uint32_t b1) {
    asm volatile(
        "mma.sync.aligned.m16n8k16.row.col.f16.f16.f16.f16 "
        "{%0,%1}, {%2,%3,%4,%5}, {%6,%7}, {%0,%1};"
        : "+r"(c0), "+r"(c1)
        : "r"(a0), "r"(a1), "r"(a2), "r"(a3), "r"(b0), "r"(b1));
}

// ---------------- prepass kernels ----------------
__global__ void k_init() {
    g_wmm[0] = 0x7fffffff; g_wmm[1] = (int)0x80000000;
    g_bmm[0] = 0x7fffffff; g_bmm[1] = (int)0x80000000;
}

// int32 weights -> fp16 (exact: |q| <= 128) + global min/max
__global__ void k_wconv(const int* __restrict__ wq) {
    int i = blockIdx.x * blockDim.x + threadIdx.x;     // one int4 per thread
    int4 v = ((const int4*)wq)[i];
    __half2 p0 = __floats2half2_rn((float)v.x, (float)v.y);
    __half2 p1 = __floats2half2_rn((float)v.z, (float)v.w);
    uint2 o;
    o.x = *(uint32_t*)&p0;
    o.y = *(uint32_t*)&p1;
    ((uint2*)g_wh)[i] = o;
    int mn = min(min(v.x, v.y), min(v.z, v.w));
    int mx = max(max(v.x, v.y), max(v.z, v.w));
    #pragma unroll
    for (int o2 = 16; o2 > 0; o2 >>= 1) {
        mn = min(mn, __shfl_xor_sync(0xffffffffu, mn, o2));
        mx = max(mx, __shfl_xor_sync(0xffffffffu, mx, o2));
    }
    if ((threadIdx.x & 31) == 0) {
        atomicMin(&g_wmm[0], mn);
        atomicMax(&g_wmm[1], mx);
    }
}

__global__ void k_bias_mm(const int* __restrict__ bq) {
    int t = threadIdx.x;
    int mn = 0x7fffffff, mx = (int)0x80000000;
    for (int i = t; i < OUT_F; i += 256) {
        int v = bq[i];
        mn = min(mn, v); mx = max(mx, v);
    }
    #pragma unroll
    for (int o = 16; o > 0; o >>= 1) {
        mn = min(mn, __shfl_xor_sync(0xffffffffu, mn, o));
        mx = max(mx, __shfl_xor_sync(0xffffffffu, mx, o));
    }
    if ((t & 31) == 0) {
        atomicMin(&g_bmm[0], mn);
        atomicMax(&g_bmm[1], mx);
    }
}

// x fp32 -> fp16 + per-row sum
__global__ void k_xcvt(const float* __restrict__ x) {
    __shared__ float red[8];
    int row = blockIdx.x;
    int t = threadIdx.x;
    const float4* xr = (const float4*)(x + (size_t)row * IN_F);
    uint32_t o[4];
    float s = 0.f;
    #pragma unroll
    for (int j = 0; j < 4; j++) {
        float4 v = xr[t * 4 + j];
        s += v.x + v.y + v.z + v.w;
        __half2 p0 = __floats2half2_rn(v.x, v.y);
        __half2 p1 = __floats2half2_rn(v.z, v.w);
        o[2 * (j & 1)]     = *(uint32_t*)&p0;
        o[2 * (j & 1) + 1] = *(uint32_t*)&p1;
        if (j & 1) {
            size_t base = ((size_t)row * IN_F) / 8 + t * 2 + (j >> 1);
            ((uint4*)g_xh)[base] = make_uint4(o[0], o[1], o[2], o[3]);
        }
    }
    #pragma unroll
    for (int of = 16; of > 0; of >>= 1) s += __shfl_xor_sync(0xffffffffu, s, of);
    if ((t & 31) == 0) red[t >> 5] = s;
    __syncthreads();
    if (t == 0) {
        float tot = 0.f;
        #pragma unroll
        for (int i = 0; i < 8; i++) tot += red[i];
        g_rowsum[row] = tot;
    }
}

__global__ void k_scal(const float* wmin, const float* wmax, const float* bmin, const float* bmax) {
    float s_w = (*wmax - *wmin) / (float)(g_wmm[1] - g_wmm[0]);
    g_scal[0] = s_w;
    g_scal[1] = *wmin - s_w * (float)g_wmm[0];
    float s_b = (*bmax - *bmin) / (float)(g_bmm[1] - g_bmm[0]);
    g_scal[2] = s_b;
    g_scal[3] = *bmin - s_b * (float)g_bmm[0];
}

// ---------------- GEMM ----------------
// CTA tile: 128 (M) x 128 (N), BK=64 fp16 (128B rows), 16 warps (4x4 of 32x32),
// 4-stage cp.async pipeline, SW128 swizzle, fp16 accumulate within a stage,
// fp32 promotion per stage (K-chunk = 64).
#define BM      128
#define BN      128
#define BK      64
#define NSTAGE  4
#define NSTEPS  (IN_F / BK)          // 64
#define A_BYTES (BM * 128)           // 16384
#define B_BYTES (BN * 128)           // 16384
#define STG_B   (A_BYTES + B_BYTES)  // 32768
#define OFF_B   A_BYTES
#define SM_TOTAL (NSTAGE * STG_B)    // 131072
#define NTHR    512

__device__ __forceinline__ void issue_stage(char* smem, int stage, int tid,
                                            const __half* asrc,
                                            const __half* bsrc, int k0) {
    uint32_t ubase = smem_u32(smem + stage * STG_B);
    // A: 128 rows x 8 chunks of 16B; 4 threads per row, 2 chunks each
    {
        int r = tid >> 2;
        int c0 = (tid & 3) * 2;
        const char* src = (const char*)(asrc + (size_t)r * IN_F + k0);
        uint32_t rb = ubase + r * 128;
        int rx = r & 7;
        #pragma unroll
        for (int c = 0; c < 2; c++)
            CP_ASYNC16(rb + (((c0 + c) ^ rx) * 16), src + (c0 + c) * 16);
    }
    // B: 128 rows x 8 chunks; 4 threads per row, 2 chunks each
    {
        int r = tid >> 2;
        int c0 = (tid & 3) * 2;
        const char* src = (const char*)(bsrc + (size_t)r * IN_F + k0);
        uint32_t rb = ubase + OFF_B + r * 128;
        int rx = r & 7;
        #pragma unroll
        for (int c = 0; c < 2; c++)
            CP_ASYNC16(rb + (((c0 + c) ^ rx) * 16), src + (c0 + c) * 16);
    }
}

__global__ void __launch_bounds__(NTHR, 1) k_gemm(const int* __restrict__ bias_q,
                                                  float* __restrict__ out) {
    extern __shared__ char smem[];
    int tid = threadIdx.x;
    int wid = tid >> 5, lid = tid & 31;
    int n0 = blockIdx.x * BN;
    int m0 = blockIdx.y * BM;
    int wm = (wid >> 2) * 32;        // warp m offset (4 slots of 32)
    int wn = (wid & 3) * 32;         // warp n offset (4 slots of 32)

    const __half* asrc = g_xh + (size_t)m0 * IN_F;
    const __half* bsrc = g_wh + (size_t)n0 * IN_F;

    float facc[2][4][4];
    uint32_t hacc[2][4][2];
    #pragma unroll
    for (int i = 0; i < 2; i++)
        #pragma unroll
        for (int j = 0; j < 4; j++) {
            hacc[i][j][0] = 0u; hacc[i][j][1] = 0u;
            #pragma unroll
            for (int q = 0; q < 4; q++) facc[i][j][q] = 0.f;
        }

    int lrow = lid & 15;
    int lkc  = (lid >> 4) & 1;       // extra 16B k-chunk for lanes 16-31
    int lx   = lrow & 7;             // swizzle xor
    uint32_t sbase = smem_u32(smem);

    uint32_t aRowOff[2], bRowOff[2];
    #pragma unroll
    for (int f = 0; f < 2; f++) {
        aRowOff[f] = (wm + f * 16 + lrow) * 128;
        bRowOff[f] = OFF_B + (wn + f * 16 + lrow) * 128;
    }

    issue_stage(smem, 0, tid, asrc, bsrc, 0);
    CP_COMMIT();
    issue_stage(smem, 1, tid, asrc, bsrc, BK);
    CP_COMMIT();
    issue_stage(smem, 2, tid, asrc, bsrc, 2 * BK);
    CP_COMMIT();

    for (int s = 0; s < NSTEPS; s++) {
        CP_WAIT(2);
        __syncthreads();
        if (s + 3 < NSTEPS)
            issue_stage(smem, (s + 3) % NSTAGE, tid, asrc, bsrc, (s + 3) * BK);
        CP_COMMIT();   // unconditional: keeps group arithmetic valid at the tail
        uint32_t stg = sbase + (s % NSTAGE) * STG_B;
        #pragma unroll
        for (int k16 = 0; k16 < 4; k16++) {
            int kc = k16 * 2 + lkc;          // 16B chunk index within 128B row
            uint32_t b[4][2];
            #pragma unroll
            for (int f = 0; f < 2; f++) {
                uint32_t q0, q1, q2, q3;
                ldsm_x4(q0, q1, q2, q3, stg + bRowOff[f] + ((kc ^ lx) * 16));
                b[2 * f][0] = q0; b[2 * f + 1][0] = q1;
                b[2 * f][1] = q2; b[2 * f + 1][1] = q3;
            }
            uint32_t a[2][4];
            #pragma unroll
            for (int f = 0; f < 2; f++)
                ldsm_x4(a[f][0], a[f][1], a[f][2], a[f][3],
                        stg + aRowOff[f] + ((kc ^ lx) * 16));
            #pragma unroll
            for (int mf = 0; mf < 2; mf++)
                #pragma unroll
                for (int nf = 0; nf < 4; nf++)
                    mma16816h(hacc[mf][nf][0], hacc[mf][nf][1],
                              a[mf][0], a[mf][1], a[mf][2], a[mf][3],
                              b[nf][0], b[nf][1]);
        }
        // promote fp16 chunk accumulators (K-chunk = 64) into fp32 and reset
        #pragma unroll
        for (int mf = 0; mf < 2; mf++)
            #pragma unroll
            for (int nf = 0; nf < 4; nf++) {
                float2 lo = __half22float2(*(__half2*)&hacc[mf][nf][0]);
                float2 hi = __half22float2(*(__half2*)&hacc[mf][nf][1]);
                facc[mf][nf][0] += lo.x;
                facc[mf][nf][1] += lo.y;
                facc[mf][nf][2] += hi.x;
                facc[mf][nf][3] += hi.y;
                hacc[mf][nf][0] = 0u;
                hacc[mf][nf][1] = 0u;
            }
        __syncthreads();
    }

    // ---------------- epilogue: y = s_w*D + off_w*rowsum + bias_deq ----------------
    float s_w = g_scal[0], off_w = g_scal[1];
    float s_b = g_scal[2], off_b = g_scal[3];
    float rs0[2], rs1[2];
    #pragma unroll
    for (int mf = 0; mf < 2; mf++) {
        int r = m0 + wm + mf * 16 + (lid >> 2);
        rs0[mf] = off_w * g_rowsum[r];
        rs1[mf] = off_w * g_rowsum[r + 8];
    }
    float bv[4][2];
    #pragma unroll
    for (int nf = 0; nf < 4; nf++) {
        int c = n0 + wn + nf * 8 + (lid & 3) * 2;
        bv[nf][0] = fmaf(s_b, (float)bias_q[c], off_b);
        bv[nf][1] = fmaf(s_b, (float)bias_q[c + 1], off_b);
    }
    #pragma unroll
    for (int mf = 0; mf < 2; mf++) {
        int r0 = m0 + wm + mf * 16 + (lid >> 2);
        #pragma unroll
        for (int nf = 0; nf < 4; nf++) {
            int c = n0 + wn + nf * 8 + (lid & 3) * 2;
            float2 v0, v1;
            v0.x = fmaf(s_w, facc[mf][nf][0], rs0[mf] + bv[nf][0]);
            v0.y = fmaf(s_w, facc[mf][nf][1], rs0[mf] + bv[nf][1]);
            v1.x = fmaf(s_w, facc[mf][nf][2], rs1[mf] + bv[nf][0]);
            v1.y = fmaf(s_w, facc[mf][nf][3], rs1[mf] + bv[nf][1]);
            *(float2*)(out + (size_t)r0 * OUT_F + c)       = v0;
            *(float2*)(out + (size_t)(r0 + 8) * OUT_F + c) = v1;
        }
    }
}

// ---------------- launch ----------------
extern "C" void kernel_launch(void* const* d_in, const int* in_sizes, int n_in,
                              void* d_out, int out_size) {
    const float* x    = (const float*)d_in[0];
    const int*   wq   = (const int*)d_in[1];
    const int*   bq   = (const int*)d_in[2];
    const float* wmin = (const float*)d_in[3];
    const float* wmax = (const float*)d_in[4];
    const float* bmin = (const float*)d_in[5];
    const float* bmax = (const float*)d_in[6];
    float* out = (float*)d_out;

    k_init<<<1, 1>>>();
    k_wconv<<<((size_t)OUT_F * IN_F / 4) / 256, 256>>>(wq);
    k_bias_mm<<<1, 256>>>(bq);
    k_xcvt<<<BATCH, 256>>>(x);
    k_scal<<<1, 1>>>(wmin, wmax, bmin, bmax);

    cudaFuncSetAttribute(k_gemm, cudaFuncAttributeMaxDynamicSharedMemorySize, SM_TOTAL);
    k_gemm<<<dim3(OUT_F / BN, BATCH / BM), NTHR, SM_TOTAL>>>(bq, out);
}

// round 8
// speedup vs baseline: 1.9681x; 1.9681x over previous
#include <cuda_runtime.h>
#include <cuda_fp16.h>
#include <stdint.h>

#define IN_F  4096
#define OUT_F 4096
#define BATCH 4096
#define KB_CNT (IN_F / 16)     // 256 k-blocks per row-block

// ---------------- scratch (static device globals; no allocation) ----------------
// Fragment-major storage: block (rb, kb) of 16 rows x 16 k is 512 bytes at
// offset ((rb * KB_CNT + kb) * 512); within it lane l owns 16B:
//   r = l>>2, c = 2*(l&3)
//   halves = { M[r][c], M[r][c+1], M[r+8][c], M[r+8][c+1],
//              M[r][c+8], M[r][c+9], M[r+8][c+8], M[r+8][c+9] }
__device__ __align__(16) __half g_wh[(size_t)OUT_F * IN_F];   // 32 MB
__device__ __align__(16) __half g_xh[(size_t)BATCH * IN_F];   // 32 MB
__device__ float g_rowsum[BATCH];
__device__ int   g_wmm[2];    // weight q min, max
__device__ int   g_bmm[2];    // bias   q min, max
__device__ float g_scal[4];   // s_w, off_w, s_b, off_b

// ---------------- PTX helpers (legal at compute_103) ----------------
__device__ __forceinline__ uint32_t smem_u32(const void* p) {
    uint32_t a;
    asm("{ .reg .u64 t; cvta.to.shared.u64 t, %1; cvt.u32.u64 %0, t; }" : "=r"(a) : "l"(p));
    return a;
}

#define CP_ASYNC16(dst, src) \
    asm volatile("cp.async.cg.shared.global [%0], [%1], 16;" :: "r"(dst), "l"(src))
#define CP_COMMIT() asm volatile("cp.async.commit_group;" ::: "memory")
#define CP_WAIT(n)  asm volatile("cp.async.wait_group %0;" :: "n"(n) : "memory")

#define LDS128(r0, r1, r2, r3, addr) \
    asm volatile("ld.shared.v4.b32 {%0,%1,%2,%3}, [%4];" \
                 : "=r"(r0), "=r"(r1), "=r"(r2), "=r"(r3) : "r"(addr))

__device__ __forceinline__ void mma16816(float& c0, float& c1, float& c2, float& c3,
                                         uint32_t a0, uint32_t a1, uint32_t a2, uint32_t a3,
                                         uint32_t b0, uint32_t b1) {
    asm volatile(
        "mma.sync.aligned.m16n8k16.row.col.f32.f16.f16.f32 "
        "{%0,%1,%2,%3}, {%4,%5,%6,%7}, {%8,%9}, {%0,%1,%2,%3};"
        : "+f"(c0), "+f"(c1), "+f"(c2), "+f"(c3)
        : "r"(a0), "r"(a1), "r"(a2), "r"(a3), "r"(b0), "r"(b1));
}

// ---------------- prepass kernels ----------------
__global__ void k_init() {
    g_wmm[0] = 0x7fffffff; g_wmm[1] = (int)0x80000000;
    g_bmm[0] = 0x7fffffff; g_bmm[1] = (int)0x80000000;
}

// int32 weights -> fp16 fragment-major blocks + global min/max.
// One warp per 16x16 block.
__global__ void k_wconv(const int* __restrict__ wq) {
    int gw = (blockIdx.x * blockDim.x + threadIdx.x) >> 5;   // block index
    int l  = threadIdx.x & 31;
    int rb = gw >> 8;            // row-block (OUT_F/16 = 256)
    int kb = gw & 255;           // k-block
    int r = l >> 2;
    int c = (l & 3) * 2;
    const int* base = wq + (size_t)(rb * 16 + r) * IN_F + kb * 16 + c;
    int2 v0 = *(const int2*)(base);                         // (r,   c..c+1)
    int2 v1 = *(const int2*)(base + 8 * IN_F);              // (r+8, c..c+1)
    int2 v2 = *(const int2*)(base + 8);                     // (r,   c+8..c+9)
    int2 v3 = *(const int2*)(base + 8 * IN_F + 8);          // (r+8, c+8..c+9)
    __half2 h0 = __floats2half2_rn((float)v0.x, (float)v0.y);
    __half2 h1 = __floats2half2_rn((float)v1.x, (float)v1.y);
    __half2 h2 = __floats2half2_rn((float)v2.x, (float)v2.y);
    __half2 h3 = __floats2half2_rn((float)v3.x, (float)v3.y);
    uint4 o = make_uint4(*(uint32_t*)&h0, *(uint32_t*)&h1, *(uint32_t*)&h2, *(uint32_t*)&h3);
    *(uint4*)((char*)g_wh + (size_t)gw * 512 + l * 16) = o;

    int mn = min(min(v0.x, v0.y), min(v1.x, v1.y));
    mn = min(mn, min(min(v2.x, v2.y), min(v3.x, v3.y)));
    int mx = max(max(v0.x, v0.y), max(v1.x, v1.y));
    mx = max(mx, max(max(v2.x, v2.y), max(v3.x, v3.y)));
    #pragma unroll
    for (int o2 = 16; o2 > 0; o2 >>= 1) {
        mn = min(mn, __shfl_xor_sync(0xffffffffu, mn, o2));
        mx = max(mx, __shfl_xor_sync(0xffffffffu, mx, o2));
    }
    if (l == 0) {
        atomicMin(&g_wmm[0], mn);
        atomicMax(&g_wmm[1], mx);
    }
}

// x fp32 -> fp16 fragment-major blocks. One warp per 16x16 block.
__global__ void k_xcvt(const float* __restrict__ x) {
    int gw = (blockIdx.x * blockDim.x + threadIdx.x) >> 5;
    int l  = threadIdx.x & 31;
    int rb = gw >> 8;
    int kb = gw & 255;
    int r = l >> 2;
    int c = (l & 3) * 2;
    const float* base = x + (size_t)(rb * 16 + r) * IN_F + kb * 16 + c;
    float2 v0 = *(const float2*)(base);
    float2 v1 = *(const float2*)(base + 8 * IN_F);
    float2 v2 = *(const float2*)(base + 8);
    float2 v3 = *(const float2*)(base + 8 * IN_F + 8);
    __half2 h0 = __floats2half2_rn(v0.x, v0.y);
    __half2 h1 = __floats2half2_rn(v1.x, v1.y);
    __half2 h2 = __floats2half2_rn(v2.x, v2.y);
    __half2 h3 = __floats2half2_rn(v3.x, v3.y);
    uint4 o = make_uint4(*(uint32_t*)&h0, *(uint32_t*)&h1, *(uint32_t*)&h2, *(uint32_t*)&h3);
    *(uint4*)((char*)g_xh + (size_t)gw * 512 + l * 16) = o;
}

// per-row sums of x (coalesced pass)
__global__ void k_rowsum(const float* __restrict__ x) {
    __shared__ float red[8];
    int row = blockIdx.x;
    int t = threadIdx.x;
    const float4* xr = (const float4*)(x + (size_t)row * IN_F);
    float s = 0.f;
    #pragma unroll
    for (int j = 0; j < 4; j++) {
        float4 v = xr[t * 4 + j];
        s += v.x + v.y + v.z + v.w;
    }
    #pragma unroll
    for (int o = 16; o > 0; o >>= 1) s += __shfl_xor_sync(0xffffffffu, s, o);
    if ((t & 31) == 0) red[t >> 5] = s;
    __syncthreads();
    if (t == 0) {
        float tot = 0.f;
        #pragma unroll
        for (int i = 0; i < 8; i++) tot += red[i];
        g_rowsum[row] = tot;
    }
}

__global__ void k_bias_mm(const int* __restrict__ bq) {
    int t = threadIdx.x;
    int mn = 0x7fffffff, mx = (int)0x80000000;
    for (int i = t; i < OUT_F; i += 256) {
        int v = bq[i];
        mn = min(mn, v); mx = max(mx, v);
    }
    #pragma unroll
    for (int o = 16; o > 0; o >>= 1) {
        mn = min(mn, __shfl_xor_sync(0xffffffffu, mn, o));
        mx = max(mx, __shfl_xor_sync(0xffffffffu, mx, o));
    }
    if ((t & 31) == 0) {
        atomicMin(&g_bmm[0], mn);
        atomicMax(&g_bmm[1], mx);
    }
}

__global__ void k_scal(const float* wmin, const float* wmax, const float* bmin, const float* bmax) {
    float s_w = (*wmax - *wmin) / (float)(g_wmm[1] - g_wmm[0]);
    g_scal[0] = s_w;
    g_scal[1] = *wmin - s_w * (float)g_wmm[0];
    float s_b = (*bmax - *bmin) / (float)(g_bmm[1] - g_bmm[0]);
    g_scal[2] = s_b;
    g_scal[3] = *bmin - s_b * (float)g_bmm[0];
}

// ---------------- GEMM ----------------
// CTA tile: 128 (M) x 128 (N), BK=64, 8 warps (2x4 of 64x32), 3-stage cp.async,
// fragment-major SMEM: LDS.128 loads fragments directly (no ldmatrix, no swizzle).
#define BM      128
#define BN      128
#define BK      64
#define NSTAGE  3
#define NSTEPS  (IN_F / BK)          // 64
#define A_BYTES (8 * 4 * 512)        // 8 m-blocks x 4 k-blocks x 512B = 16384
#define B_BYTES (8 * 4 * 512)        // 16384
#define STG_B   (A_BYTES + B_BYTES)  // 32768
#define OFF_B   A_BYTES
#define SM_TOTAL (NSTAGE * STG_B)    // 98304
#define NTHR    256

__device__ __forceinline__ void issue_stage(char* smem, int stage, int tid,
                                            const char* abase, const char* bbase, int s) {
    uint32_t ubase = smem_u32(smem + stage * STG_B);
    // 1024 16B chunks each for A and B; 256 threads x 4 chunks each.
    #pragma unroll
    for (int j = 0; j < 4; j++) {
        int ch = j * 256 + tid;                  // 0..1023
        int mb   = ch >> 7;                      // local 16-row block 0..7
        int kb   = (ch >> 5) & 3;                // local k-block 0..3
        int lane = ch & 31;
        size_t goff = ((size_t)mb * KB_CNT + (size_t)(s * 4 + kb)) * 512 + lane * 16;
        CP_ASYNC16(ubase + ch * 16,         abase + goff);
        CP_ASYNC16(ubase + OFF_B + ch * 16, bbase + goff);
    }
}

__global__ void __launch_bounds__(NTHR, 2) k_gemm(const int* __restrict__ bias_q,
                                                  float* __restrict__ out) {
    extern __shared__ char smem[];
    int tid = threadIdx.x;
    int wid = tid >> 5, lid = tid & 31;
    int n0 = blockIdx.x * BN;
    int m0 = blockIdx.y * BM;
    int wm = (wid >> 2) * 64;        // warp m offset (2 slots of 64)
    int wn = (wid & 3) * 32;         // warp n offset (4 slots of 32)

    // block-major bases for this CTA's row-block ranges
    const char* abase = (const char*)g_xh + (size_t)(m0 / 16) * KB_CNT * 512;
    const char* bbase = (const char*)g_wh + (size_t)(n0 / 16) * KB_CNT * 512;

    float acc[4][4][4];
    #pragma unroll
    for (int i = 0; i < 4; i++)
        #pragma unroll
        for (int j = 0; j < 4; j++)
            #pragma unroll
            for (int q = 0; q < 4; q++) acc[i][j][q] = 0.f;

    uint32_t sbase = smem_u32(smem);
    uint32_t lane16 = lid * 16;
    // per-warp block offsets within a stage (block index * 512)
    uint32_t aBlk[4], bBlk[2];
    #pragma unroll
    for (int f = 0; f < 4; f++) aBlk[f] = ((wm >> 4) + f) * 4 * 512;
    #pragma unroll
    for (int g = 0; g < 2; g++) bBlk[g] = OFF_B + (((wn >> 4) + g) * 4) * 512;

    issue_stage(smem, 0, tid, abase, bbase, 0);
    CP_COMMIT();
    issue_stage(smem, 1, tid, abase, bbase, 1);
    CP_COMMIT();

    for (int s = 0; s < NSTEPS; s++) {
        CP_WAIT(1);
        __syncthreads();
        if (s + 2 < NSTEPS)
            issue_stage(smem, (s + 2) % NSTAGE, tid, abase, bbase, s + 2);
        CP_COMMIT();   // unconditional: keeps group arithmetic valid at the tail
        uint32_t stg = sbase + (s % NSTAGE) * STG_B;
        #pragma unroll
        for (int kb = 0; kb < 4; kb++) {
            uint32_t koff = kb * 512 + lane16;
            // B: 2 blocks of 16 cols -> 4 n8 fragments
            uint32_t b[4][2];
            #pragma unroll
            for (int g = 0; g < 2; g++) {
                uint32_t q0, q1, q2, q3;
                LDS128(q0, q1, q2, q3, stg + bBlk[g] + koff);
                b[2 * g][0] = q0; b[2 * g][1] = q2;      // n-lo frag
                b[2 * g + 1][0] = q1; b[2 * g + 1][1] = q3;  // n-hi frag
            }
            // A: 4 blocks of 16 rows
            uint32_t a[4][4];
            #pragma unroll
            for (int f = 0; f < 4; f++)
                LDS128(a[f][0], a[f][1], a[f][2], a[f][3], stg + aBlk[f] + koff);
            #pragma unroll
            for (int mf = 0; mf < 4; mf++)
                #pragma unroll
                for (int nf = 0; nf < 4; nf++)
                    mma16816(acc[mf][nf][0], acc[mf][nf][1], acc[mf][nf][2], acc[mf][nf][3],
                             a[mf][0], a[mf][1], a[mf][2], a[mf][3],
                             b[nf][0], b[nf][1]);
        }
        __syncthreads();
    }

    // ---------------- epilogue: y = s_w*D + off_w*rowsum + bias_deq ----------------
    float s_w = g_scal[0], off_w = g_scal[1];
    float s_b = g_scal[2], off_b = g_scal[3];
    float rs0[4], rs1[4];
    #pragma unroll
    for (int mf = 0; mf < 4; mf++) {
        int r = m0 + wm + mf * 16 + (lid >> 2);
        rs0[mf] = off_w * g_rowsum[r];
        rs1[mf] = off_w * g_rowsum[r + 8];
    }
    float bv[4][2];
    #pragma unroll
    for (int nf = 0; nf < 4; nf++) {
        int c = n0 + wn + nf * 8 + (lid & 3) * 2;
        bv[nf][0] = fmaf(s_b, (float)bias_q[c], off_b);
        bv[nf][1] = fmaf(s_b, (float)bias_q[c + 1], off_b);
    }
    #pragma unroll
    for (int mf = 0; mf < 4; mf++) {
        int r0 = m0 + wm + mf * 16 + (lid >> 2);
        #pragma unroll
        for (int nf = 0; nf < 4; nf++) {
            int c = n0 + wn + nf * 8 + (lid & 3) * 2;
            float2 v0, v1;
            v0.x = fmaf(s_w, acc[mf][nf][0], rs0[mf] + bv[nf][0]);
            v0.y = fmaf(s_w, acc[mf][nf][1], rs0[mf] + bv[nf][1]);
            v1.x = fmaf(s_w, acc[mf][nf][2], rs1[mf] + bv[nf][0]);
            v1.y = fmaf(s_w, acc[mf][nf][3], rs1[mf] + bv[nf][1]);
            *(float2*)(out + (size_t)r0 * OUT_F + c)       = v0;
            *(float2*)(out + (size_t)(r0 + 8) * OUT_F + c) = v1;
        }
    }
}

// ---------------- launch ----------------
extern "C" void kernel_launch(void* const* d_in, const int* in_sizes, int n_in,
                              void* d_out, int out_size) {
    const float* x    = (const float*)d_in[0];
    const int*   wq   = (const int*)d_in[1];
    const int*   bq   = (const int*)d_in[2];
    const float* wmin = (const float*)d_in[3];
    const float* wmax = (const float*)d_in[4];
    const float* bmin = (const float*)d_in[5];
    const float* bmax = (const float*)d_in[6];
    float* out = (float*)d_out;

    k_init<<<1, 1>>>();
    // 256x256 blocks per matrix, 8 warps (blocks of 256 threads) each handle 8 blocks
    k_wconv<<<(256 * 256) / 8, 256>>>(wq);
    k_xcvt<<<(256 * 256) / 8, 256>>>(x);
    k_rowsum<<<BATCH, 256>>>(x);
    k_bias_mm<<<1, 256>>>(bq);
    k_scal<<<1, 1>>>(wmin, wmax, bmin, bmax);

    cudaFuncSetAttribute(k_gemm, cudaFuncAttributeMaxDynamicSharedMemorySize, SM_TOTAL);
    k_gemm<<<dim3(OUT_F / BN, BATCH / BM), NTHR, SM_TOTAL>>>(bq, out);
}

// round 9
// speedup vs baseline: 2.0303x; 1.0316x over previous
#include <cuda_runtime.h>
#include <cuda_fp16.h>
#include <stdint.h>

#define IN_F  4096
#define OUT_F 4096
#define BATCH 4096
#define KB_CNT (IN_F / 16)     // 256 k-blocks per row-block

// ---------------- scratch (static device globals; no allocation) ----------------
// Fragment-major storage: block (rb, kb) of 16 rows x 16 k is 512 bytes at
// offset ((rb * KB_CNT + kb) * 512); within it lane l owns 16B:
//   r = l>>2, c = 2*(l&3)
//   halves = { M[r][c], M[r][c+1], M[r+8][c], M[r+8][c+1],
//              M[r][c+8], M[r][c+9], M[r+8][c+8], M[r+8][c+9] }
__device__ __align__(16) __half g_wh[(size_t)OUT_F * IN_F];   // 32 MB
__device__ __align__(16) __half g_xh[(size_t)BATCH * IN_F];   // 32 MB
__device__ float g_rowsum[BATCH];
__device__ int   g_wmm[2];    // weight q min, max
__device__ int   g_bmm[2];    // bias   q min, max
__device__ float g_scal[4];   // s_w, off_w, s_b, off_b

// ---------------- PTX helpers (legal at compute_103) ----------------
__device__ __forceinline__ uint32_t smem_u32(const void* p) {
    uint32_t a;
    asm("{ .reg .u64 t; cvta.to.shared.u64 t, %1; cvt.u32.u64 %0, t; }" : "=r"(a) : "l"(p));
    return a;
}

#define CP_ASYNC16(dst, src) \
    asm volatile("cp.async.cg.shared.global [%0], [%1], 16;" :: "r"(dst), "l"(src))
#define CP_COMMIT() asm volatile("cp.async.commit_group;" ::: "memory")
#define CP_WAIT(n)  asm volatile("cp.async.wait_group %0;" :: "n"(n) : "memory")

#define LDS128(r0, r1, r2, r3, addr) \
    asm volatile("ld.shared.v4.b32 {%0,%1,%2,%3}, [%4];" \
                 : "=r"(r0), "=r"(r1), "=r"(r2), "=r"(r3) : "r"(addr))

__device__ __forceinline__ void mma16816(float& c0, float& c1, float& c2, float& c3,
                                         uint32_t a0, uint32_t a1, uint32_t a2, uint32_t a3,
                                         uint32_t b0, uint32_t b1) {
    asm volatile(
        "mma.sync.aligned.m16n8k16.row.col.f32.f16.f16.f32 "
        "{%0,%1,%2,%3}, {%4,%5,%6,%7}, {%8,%9}, {%0,%1,%2,%3};"
        : "+f"(c0), "+f"(c1), "+f"(c2), "+f"(c3)
        : "r"(a0), "r"(a1), "r"(a2), "r"(a3), "r"(b0), "r"(b1));
}

// ---------------- prepass kernels ----------------
__global__ void k_init() {
    g_wmm[0] = 0x7fffffff; g_wmm[1] = (int)0x80000000;
    g_bmm[0] = 0x7fffffff; g_bmm[1] = (int)0x80000000;
}

// int32 weights -> fp16 fragment-major blocks + global min/max.
// One warp per 16x16 block.
__global__ void k_wconv(const int* __restrict__ wq) {
    int gw = (blockIdx.x * blockDim.x + threadIdx.x) >> 5;   // block index
    int l  = threadIdx.x & 31;
    int rb = gw >> 8;            // row-block (OUT_F/16 = 256)
    int kb = gw & 255;           // k-block
    int r = l >> 2;
    int c = (l & 3) * 2;
    const int* base = wq + (size_t)(rb * 16 + r) * IN_F + kb * 16 + c;
    int2 v0 = *(const int2*)(base);                         // (r,   c..c+1)
    int2 v1 = *(const int2*)(base + 8 * IN_F);              // (r+8, c..c+1)
    int2 v2 = *(const int2*)(base + 8);                     // (r,   c+8..c+9)
    int2 v3 = *(const int2*)(base + 8 * IN_F + 8);          // (r+8, c+8..c+9)
    __half2 h0 = __floats2half2_rn((float)v0.x, (float)v0.y);
    __half2 h1 = __floats2half2_rn((float)v1.x, (float)v1.y);
    __half2 h2 = __floats2half2_rn((float)v2.x, (float)v2.y);
    __half2 h3 = __floats2half2_rn((float)v3.x, (float)v3.y);
    uint4 o = make_uint4(*(uint32_t*)&h0, *(uint32_t*)&h1, *(uint32_t*)&h2, *(uint32_t*)&h3);
    *(uint4*)((char*)g_wh + (size_t)gw * 512 + l * 16) = o;

    int mn = min(min(v0.x, v0.y), min(v1.x, v1.y));
    mn = min(mn, min(min(v2.x, v2.y), min(v3.x, v3.y)));
    int mx = max(max(v0.x, v0.y), max(v1.x, v1.y));
    mx = max(mx, max(max(v2.x, v2.y), max(v3.x, v3.y)));
    #pragma unroll
    for (int o2 = 16; o2 > 0; o2 >>= 1) {
        mn = min(mn, __shfl_xor_sync(0xffffffffu, mn, o2));
        mx = max(mx, __shfl_xor_sync(0xffffffffu, mx, o2));
    }
    if (l == 0) {
        atomicMin(&g_wmm[0], mn);
        atomicMax(&g_wmm[1], mx);
    }
}

// x fp32 -> fp16 fragment-major blocks. One warp per 16x16 block.
__global__ void k_xcvt(const float* __restrict__ x) {
    int gw = (blockIdx.x * blockDim.x + threadIdx.x) >> 5;
    int l  = threadIdx.x & 31;
    int rb = gw >> 8;
    int kb = gw & 255;
    int r = l >> 2;
    int c = (l & 3) * 2;
    const float* base = x + (size_t)(rb * 16 + r) * IN_F + kb * 16 + c;
    float2 v0 = *(const float2*)(base);
    float2 v1 = *(const float2*)(base + 8 * IN_F);
    float2 v2 = *(const float2*)(base + 8);
    float2 v3 = *(const float2*)(base + 8 * IN_F + 8);
    __half2 h0 = __floats2half2_rn(v0.x, v0.y);
    __half2 h1 = __floats2half2_rn(v1.x, v1.y);
    __half2 h2 = __floats2half2_rn(v2.x, v2.y);
    __half2 h3 = __floats2half2_rn(v3.x, v3.y);
    uint4 o = make_uint4(*(uint32_t*)&h0, *(uint32_t*)&h1, *(uint32_t*)&h2, *(uint32_t*)&h3);
    *(uint4*)((char*)g_xh + (size_t)gw * 512 + l * 16) = o;
}

// per-row sums of x (coalesced pass)
__global__ void k_rowsum(const float* __restrict__ x) {
    __shared__ float red[8];
    int row = blockIdx.x;
    int t = threadIdx.x;
    const float4* xr = (const float4*)(x + (size_t)row * IN_F);
    float s = 0.f;
    #pragma unroll
    for (int j = 0; j < 4; j++) {
        float4 v = xr[t * 4 + j];
        s += v.x + v.y + v.z + v.w;
    }
    #pragma unroll
    for (int o = 16; o > 0; o >>= 1) s += __shfl_xor_sync(0xffffffffu, s, o);
    if ((t & 31) == 0) red[t >> 5] = s;
    __syncthreads();
    if (t == 0) {
        float tot = 0.f;
        #pragma unroll
        for (int i = 0; i < 8; i++) tot += red[i];
        g_rowsum[row] = tot;
    }
}

__global__ void k_bias_mm(const int* __restrict__ bq) {
    int t = threadIdx.x;
    int mn = 0x7fffffff, mx = (int)0x80000000;
    for (int i = t; i < OUT_F; i += 256) {
        int v = bq[i];
        mn = min(mn, v); mx = max(mx, v);
    }
    #pragma unroll
    for (int o = 16; o > 0; o >>= 1) {
        mn = min(mn, __shfl_xor_sync(0xffffffffu, mn, o));
        mx = max(mx, __shfl_xor_sync(0xffffffffu, mx, o));
    }
    if ((t & 31) == 0) {
        atomicMin(&g_bmm[0], mn);
        atomicMax(&g_bmm[1], mx);
    }
}

__global__ void k_scal(const float* wmin, const float* wmax, const float* bmin, const float* bmax) {
    float s_w = (*wmax - *wmin) / (float)(g_wmm[1] - g_wmm[0]);
    g_scal[0] = s_w;
    g_scal[1] = *wmin - s_w * (float)g_wmm[0];
    float s_b = (*bmax - *bmin) / (float)(g_bmm[1] - g_bmm[0]);
    g_scal[2] = s_b;
    g_scal[3] = *bmin - s_b * (float)g_bmm[0];
}

// ---------------- GEMM ----------------
// CTA tile: 128 (M) x 128 (N), BK=64, 4 warps (2x2 of 64x64), 3-stage cp.async,
// fragment-major SMEM, LDS.128 fragment loads, register double-buffering.
#define BM      128
#define BN      128
#define BK      64
#define NSTAGE  3
#define NSTEPS  (IN_F / BK)          // 64
#define A_BYTES (8 * 4 * 512)        // 8 m-blocks x 4 k-blocks x 512B = 16384
#define B_BYTES (8 * 4 * 512)        // 16384
#define STG_B   (A_BYTES + B_BYTES)  // 32768
#define OFF_B   A_BYTES
#define SM_TOTAL (NSTAGE * STG_B)    // 98304
#define NTHR    128

__device__ __forceinline__ void issue_stage(char* smem, int stage, int tid,
                                            const char* abase, const char* bbase, int s) {
    uint32_t ubase = smem_u32(smem + stage * STG_B);
    // 1024 16B chunks each for A and B; 128 threads x 8 chunks each.
    #pragma unroll
    for (int j = 0; j < 8; j++) {
        int ch = j * 128 + tid;                  // 0..1023
        int mb   = ch >> 7;                      // local 16-row block 0..7
        int kb   = (ch >> 5) & 3;                // local k-block 0..3
        int lane = ch & 31;
        size_t goff = ((size_t)mb * KB_CNT + (size_t)(s * 4 + kb)) * 512 + lane * 16;
        CP_ASYNC16(ubase + ch * 16,         abase + goff);
        CP_ASYNC16(ubase + OFF_B + ch * 16, bbase + goff);
    }
}

__global__ void __launch_bounds__(NTHR, 2) k_gemm(const int* __restrict__ bias_q,
                                                  float* __restrict__ out) {
    extern __shared__ char smem[];
    int tid = threadIdx.x;
    int wid = tid >> 5, lid = tid & 31;
    int n0 = blockIdx.x * BN;
    int m0 = blockIdx.y * BM;
    int wm = (wid >> 1) * 64;        // warp m offset (2 slots of 64)
    int wn = (wid & 1) * 64;         // warp n offset (2 slots of 64)

    const char* abase = (const char*)g_xh + (size_t)(m0 / 16) * KB_CNT * 512;
    const char* bbase = (const char*)g_wh + (size_t)(n0 / 16) * KB_CNT * 512;

    float acc[4][8][4];
    #pragma unroll
    for (int i = 0; i < 4; i++)
        #pragma unroll
        for (int j = 0; j < 8; j++)
            #pragma unroll
            for (int q = 0; q < 4; q++) acc[i][j][q] = 0.f;

    uint32_t sbase = smem_u32(smem);
    uint32_t lane16 = lid * 16;
    uint32_t aBlk[4], bBlk[4];
    #pragma unroll
    for (int f = 0; f < 4; f++) {
        aBlk[f] = ((wm >> 4) + f) * 4 * 512 + lane16;
        bBlk[f] = OFF_B + ((wn >> 4) + f) * 4 * 512 + lane16;
    }

    issue_stage(smem, 0, tid, abase, bbase, 0);
    CP_COMMIT();
    issue_stage(smem, 1, tid, abase, bbase, 1);
    CP_COMMIT();

    uint32_t aC[4][4], bC[4][4], aN[4][4], bN[4][4];

    for (int s = 0; s < NSTEPS; s++) {
        CP_WAIT(1);
        __syncthreads();
        if (s + 2 < NSTEPS)
            issue_stage(smem, (s + 2) % NSTAGE, tid, abase, bbase, s + 2);
        CP_COMMIT();   // unconditional: keeps group arithmetic valid at the tail
        uint32_t stg = sbase + (s % NSTAGE) * STG_B;

        // prime kb=0 fragments
        #pragma unroll
        for (int f = 0; f < 4; f++) {
            LDS128(aC[f][0], aC[f][1], aC[f][2], aC[f][3], stg + aBlk[f]);
            LDS128(bC[f][0], bC[f][1], bC[f][2], bC[f][3], stg + bBlk[f]);
        }
        #pragma unroll
        for (int kb = 0; kb < 4; kb++) {
            if (kb < 3) {
                uint32_t koff = (kb + 1) * 512;
                #pragma unroll
                for (int f = 0; f < 4; f++) {
                    LDS128(aN[f][0], aN[f][1], aN[f][2], aN[f][3], stg + aBlk[f] + koff);
                    LDS128(bN[f][0], bN[f][1], bN[f][2], bN[f][3], stg + bBlk[f] + koff);
                }
            }
            #pragma unroll
            for (int mf = 0; mf < 4; mf++)
                #pragma unroll
                for (int g = 0; g < 4; g++) {
                    // B block g supplies n8 frags 2g (lo: q0,q2) and 2g+1 (hi: q1,q3)
                    mma16816(acc[mf][2*g][0], acc[mf][2*g][1], acc[mf][2*g][2], acc[mf][2*g][3],
                             aC[mf][0], aC[mf][1], aC[mf][2], aC[mf][3],
                             bC[g][0], bC[g][2]);
                    mma16816(acc[mf][2*g+1][0], acc[mf][2*g+1][1], acc[mf][2*g+1][2], acc[mf][2*g+1][3],
                             aC[mf][0], aC[mf][1], aC[mf][2], aC[mf][3],
                             bC[g][1], bC[g][3]);
                }
            if (kb < 3) {
                #pragma unroll
                for (int f = 0; f < 4; f++)
                    #pragma unroll
                    for (int q = 0; q < 4; q++) {
                        aC[f][q] = aN[f][q];
                        bC[f][q] = bN[f][q];
                    }
            }
        }
        __syncthreads();
    }

    // ---------------- epilogue: y = s_w*D + off_w*rowsum + bias_deq ----------------
    float s_w = g_scal[0], off_w = g_scal[1];
    float s_b = g_scal[2], off_b = g_scal[3];
    float rs0[4], rs1[4];
    #pragma unroll
    for (int mf = 0; mf < 4; mf++) {
        int r = m0 + wm + mf * 16 + (lid >> 2);
        rs0[mf] = off_w * g_rowsum[r];
        rs1[mf] = off_w * g_rowsum[r + 8];
    }
    float bv[8][2];
    #pragma unroll
    for (int nf = 0; nf < 8; nf++) {
        int c = n0 + wn + nf * 8 + (lid & 3) * 2;
        bv[nf][0] = fmaf(s_b, (float)bias_q[c], off_b);
        bv[nf][1] = fmaf(s_b, (float)bias_q[c + 1], off_b);
    }
    #pragma unroll
    for (int mf = 0; mf < 4; mf++) {
        int r0 = m0 + wm + mf * 16 + (lid >> 2);
        #pragma unroll
        for (int nf = 0; nf < 8; nf++) {
            int c = n0 + wn + nf * 8 + (lid & 3) * 2;
            float2 v0, v1;
            v0.x = fmaf(s_w, acc[mf][nf][0], rs0[mf] + bv[nf][0]);
            v0.y = fmaf(s_w, acc[mf][nf][1], rs0[mf] + bv[nf][1]);
            v1.x = fmaf(s_w, acc[mf][nf][2], rs1[mf] + bv[nf][0]);
            v1.y = fmaf(s_w, acc[mf][nf][3], rs1[mf] + bv[nf][1]);
            *(float2*)(out + (size_t)r0 * OUT_F + c)       = v0;
            *(float2*)(out + (size_t)(r0 + 8) * OUT_F + c) = v1;
        }
    }
}

// ---------------- launch ----------------
extern "C" void kernel_launch(void* const* d_in, const int* in_sizes, int n_in,
                              void* d_out, int out_size) {
    const float* x    = (const float*)d_in[0];
    const int*   wq   = (const int*)d_in[1];
    const int*   bq   = (const int*)d_in[2];
    const float* wmin = (const float*)d_in[3];
    const float* wmax = (const float*)d_in[4];
    const float* bmin = (const float*)d_in[5];
    const float* bmax = (const float*)d_in[6];
    float* out = (float*)d_out;

    k_init<<<1, 1>>>();
    k_wconv<<<(256 * 256) / 8, 256>>>(wq);
    k_xcvt<<<(256 * 256) / 8, 256>>>(x);
    k_rowsum<<<BATCH, 256>>>(x);
    k_bias_mm<<<1, 256>>>(bq);
    k_scal<<<1, 1>>>(wmin, wmax, bmin, bmax);

    cudaFuncSetAttribute(k_gemm, cudaFuncAttributeMaxDynamicSharedMemorySize, SM_TOTAL);
    k_gemm<<<dim3(OUT_F / BN, BATCH / BM), NTHR, SM_TOTAL>>>(bq, out);
}